// round 4
// baseline (speedup 1.0000x reference)
#include <cuda_runtime.h>

// ---------------------------------------------------------------------------
// Problem constants (shapes fixed by the dataset; runtime sizes still honored)
// ---------------------------------------------------------------------------
#define NMAX 50000
#define DF   128   // in feats = out feats

// Device scratch (static __device__ arrays: allocation-free per harness rules)
__device__ float g_neigh[NMAX * DF];   // 25.6 MB
__device__ float g_deg[NMAX];
__device__ float g_sum[DF];
__device__ float g_sumsq[DF];
__device__ float g_scale[DF];
__device__ float g_shift[DF];

// ---------------------------------------------------------------------------
// 1) Zero scratch
// ---------------------------------------------------------------------------
__global__ void zero_kernel(int N) {
    int tid = blockIdx.x * blockDim.x + threadIdx.x;
    int stride = gridDim.x * blockDim.x;
    int total4 = N * (DF / 4);
    float4 z = make_float4(0.f, 0.f, 0.f, 0.f);
    float4* n4 = reinterpret_cast<float4*>(g_neigh);
    for (int i = tid; i < total4; i += stride) n4[i] = z;
    for (int i = tid; i < N; i += stride) g_deg[i] = 0.f;
    if (blockIdx.x == 0 && threadIdx.x < DF) {
        g_sum[threadIdx.x] = 0.f;
        g_sumsq[threadIdx.x] = 0.f;
    }
}

// ---------------------------------------------------------------------------
// 2) Edge aggregation: one warp per edge.
//    neigh[dst] += feat[src] * w ; deg[dst] += w
// ---------------------------------------------------------------------------
__global__ void agg_kernel(const float* __restrict__ feat,
                           const int* __restrict__ src,
                           const int* __restrict__ dst,
                           const float* __restrict__ ew,
                           int E) {
    int warp = (blockIdx.x * blockDim.x + threadIdx.x) >> 5;
    int lane = threadIdx.x & 31;
    if (warp >= E) return;
    int s = __ldg(&src[warp]);
    int d = __ldg(&dst[warp]);
    float w = __ldg(&ew[warp]);
    const float4 v = *reinterpret_cast<const float4*>(feat + (size_t)s * DF + lane * 4);
    float* nb = g_neigh + (size_t)d * DF + lane * 4;
    atomicAdd(nb + 0, v.x * w);
    atomicAdd(nb + 1, v.y * w);
    atomicAdd(nb + 2, v.z * w);
    atomicAdd(nb + 3, v.w * w);
    if (lane == 0) atomicAdd(&g_deg[d], w);
}

// ---------------------------------------------------------------------------
// 3) Fused dual GEMM + bias + ReLU.
//    out[r, o] = relu( sum_d feat[r,d] * Wself[o,d]
//                    + sum_d (neigh[r,d]/(deg[r]+eps)) * Wneigh[o,d]
//                    + b_self[o] + bias[o] )
//    Treated as a single [N,256] @ [256,128] GEMM with concatenated A and W.
//    Both weight matrices live in shared memory; persistent 148-block grid.
//    Block tile: 64 rows x 128 cols; thread micro-tile: 8 rows x 4 cols.
// ---------------------------------------------------------------------------
#define TM 64
#define WS_STRIDE 132                       // 128 + 4 pad (float4-aligned, avoids STS conflicts)
#define WS_FLOATS (256 * WS_STRIDE)         // 33792
#define AS_FLOATS (TM * 256)                // 16384
#define SMEM_FLOATS (WS_FLOATS + AS_FLOATS + TM)
#define SMEM_BYTES (SMEM_FLOATS * 4)        // 200,960 bytes

__global__ __launch_bounds__(256, 1)
void gemm_kernel(const float* __restrict__ feat,
                 const float* __restrict__ Wneigh,
                 const float* __restrict__ Wself,
                 const float* __restrict__ b_self,
                 const float* __restrict__ bias,
                 float* __restrict__ out,
                 int N) {
    extern __shared__ float sm[];
    float* Ws  = sm;                      // [256][WS_STRIDE], k-major
    float* As  = sm + WS_FLOATS;          // [TM][256], row-major
    float* sInv = As + AS_FLOATS;         // [TM]

    const int tid = threadIdx.x;
    const int ty = tid >> 5;              // 0..7  -> row group
    const int tx = tid & 31;              // 0..31 -> col group (cols tx*4..tx*4+3)

    // Load both weight matrices (transposed to k-major) once per block.
    for (int idx = tid; idx < DF * DF; idx += 256) {
        int o = idx >> 7;                 // output channel
        int d = idx & 127;                // input channel
        Ws[d * WS_STRIDE + o]          = Wself[idx];   // k = d       (feat part)
        Ws[(DF + d) * WS_STRIDE + o]   = Wneigh[idx];  // k = 128 + d (neigh part)
    }
    float bc[4];
#pragma unroll
    for (int c = 0; c < 4; c++) {
        int col = tx * 4 + c;
        bc[c] = __ldg(&b_self[col]) + __ldg(&bias[col]);
    }

    const int ntiles = (N + TM - 1) / TM;
    for (int tile = blockIdx.x; tile < ntiles; tile += gridDim.x) {
        const int row0 = tile * TM;
        const int rows = min(TM, N - row0);

        __syncthreads();   // previous tile's smem reads done / weight load done
        if (tid < rows) sInv[tid] = 1.0f / (g_deg[row0 + tid] + 1e-8f);
        __syncthreads();

        // Fill A tile: [0,128) = feat row, [128,256) = normalized neigh row
        for (int idx = tid; idx < rows * 256; idx += 256) {
            int r = idx >> 8;
            int k = idx & 255;
            float v;
            if (k < DF) v = feat[(size_t)(row0 + r) * DF + k];
            else        v = g_neigh[(size_t)(row0 + r) * DF + (k - DF)] * sInv[r];
            As[r * 256 + k] = v;
        }
        __syncthreads();

        float acc[8][4];
#pragma unroll
        for (int j = 0; j < 8; j++)
#pragma unroll
            for (int c = 0; c < 4; c++) acc[j][c] = 0.f;

        for (int k = 0; k < 256; k += 4) {
            float4 a4[8];
#pragma unroll
            for (int j = 0; j < 8; j++)
                a4[j] = *reinterpret_cast<const float4*>(&As[(ty + 8 * j) * 256 + k]);
#pragma unroll
            for (int kk = 0; kk < 4; kk++) {
                const float4 w = *reinterpret_cast<const float4*>(
                    &Ws[(k + kk) * WS_STRIDE + tx * 4]);
#pragma unroll
                for (int j = 0; j < 8; j++) {
                    float a = (kk == 0) ? a4[j].x : (kk == 1) ? a4[j].y
                              : (kk == 2) ? a4[j].z : a4[j].w;
                    acc[j][0] = fmaf(a, w.x, acc[j][0]);
                    acc[j][1] = fmaf(a, w.y, acc[j][1]);
                    acc[j][2] = fmaf(a, w.z, acc[j][2]);
                    acc[j][3] = fmaf(a, w.w, acc[j][3]);
                }
            }
        }

        // Epilogue: bias + ReLU, store
#pragma unroll
        for (int j = 0; j < 8; j++) {
            int rl = ty + 8 * j;
            if (rl < rows) {
                float4 o4;
                o4.x = fmaxf(acc[j][0] + bc[0], 0.f);
                o4.y = fmaxf(acc[j][1] + bc[1], 0.f);
                o4.z = fmaxf(acc[j][2] + bc[2], 0.f);
                o4.w = fmaxf(acc[j][3] + bc[3], 0.f);
                *reinterpret_cast<float4*>(&out[(size_t)(row0 + rl) * DF + tx * 4]) = o4;
            }
        }
    }
}

// ---------------------------------------------------------------------------
// 4) BatchNorm column statistics (sum, sum of squares)
// ---------------------------------------------------------------------------
__global__ void stats_kernel(const float* __restrict__ out, int N) {
    int c = threadIdx.x;   // 128 threads
    float s = 0.f, sq = 0.f;
    for (int r = blockIdx.x; r < N; r += gridDim.x) {
        float v = out[(size_t)r * DF + c];
        s += v;
        sq += v * v;
    }
    atomicAdd(&g_sum[c], s);
    atomicAdd(&g_sumsq[c], sq);
}

// ---------------------------------------------------------------------------
// 5) Finalize BN scale/shift
// ---------------------------------------------------------------------------
__global__ void finalize_kernel(const float* __restrict__ gamma,
                                const float* __restrict__ beta, int N) {
    int c = threadIdx.x;
    if (c < DF) {
        float invn = 1.0f / (float)N;
        float mu = g_sum[c] * invn;
        float var = g_sumsq[c] * invn - mu * mu;
        float rs = rsqrtf(var + 1e-5f);
        float sc = gamma[c] * rs;
        g_scale[c] = sc;
        g_shift[c] = beta[c] - mu * sc;
    }
}

// ---------------------------------------------------------------------------
// 6) Apply BN in place on out
// ---------------------------------------------------------------------------
__global__ void norm_kernel(float* __restrict__ out, int N) {
    int tid = blockIdx.x * blockDim.x + threadIdx.x;
    int stride = gridDim.x * blockDim.x;
    int total4 = N * (DF / 4);
    float4* o4 = reinterpret_cast<float4*>(out);
    for (int i = tid; i < total4; i += stride) {
        int col = (i & 31) * 4;     // 32 float4 per row
        float4 v = o4[i];
        v.x = v.x * g_scale[col + 0] + g_shift[col + 0];
        v.y = v.y * g_scale[col + 1] + g_shift[col + 1];
        v.z = v.z * g_scale[col + 2] + g_shift[col + 2];
        v.w = v.w * g_scale[col + 3] + g_shift[col + 3];
        o4[i] = v;
    }
}

// ---------------------------------------------------------------------------
// Launch
// Inputs (metadata order): feat, src, dst, edge_weight, W_neigh, W_self,
//                          b_self, bias, gamma, beta
// ---------------------------------------------------------------------------
extern "C" void kernel_launch(void* const* d_in, const int* in_sizes, int n_in,
                              void* d_out, int out_size) {
    const float* feat   = (const float*)d_in[0];
    const int*   src    = (const int*)  d_in[1];
    const int*   dst    = (const int*)  d_in[2];
    const float* ew     = (const float*)d_in[3];
    const float* Wneigh = (const float*)d_in[4];
    const float* Wself  = (const float*)d_in[5];
    const float* b_self = (const float*)d_in[6];
    const float* bias   = (const float*)d_in[7];
    const float* gamma  = (const float*)d_in[8];
    const float* beta   = (const float*)d_in[9];
    float* out = (float*)d_out;

    const int N = in_sizes[0] / DF;
    const int E = in_sizes[1];

    cudaFuncSetAttribute(gemm_kernel,
                         cudaFuncAttributeMaxDynamicSharedMemorySize, SMEM_BYTES);

    zero_kernel<<<2048, 256>>>(N);
    agg_kernel<<<(E + 7) / 8, 256>>>(feat, src, dst, ew, E);
    gemm_kernel<<<148, 256, SMEM_BYTES>>>(feat, Wneigh, Wself, b_self, bias, out, N);
    stats_kernel<<<512, 128>>>(out, N);
    finalize_kernel<<<1, 128>>>(gamma, beta, N);
    norm_kernel<<<2048, 256>>>(out, N);
}

// round 5
// speedup vs baseline: 1.5944x; 1.5944x over previous
#include <cuda_runtime.h>

#define NMAX 50000
#define DF   128

__device__ float g_neigh[NMAX * DF];
__device__ float g_deg[NMAX];
__device__ float g_sum[DF];
__device__ float g_sumsq[DF];
__device__ float g_scale[DF];
__device__ float g_shift[DF];

// ---------------------------------------------------------------------------
// 1) Zero scratch
// ---------------------------------------------------------------------------
__global__ void zero_kernel(int N) {
    int tid = blockIdx.x * blockDim.x + threadIdx.x;
    int stride = gridDim.x * blockDim.x;
    int total4 = N * (DF / 4);
    float4 z = make_float4(0.f, 0.f, 0.f, 0.f);
    float4* n4 = reinterpret_cast<float4*>(g_neigh);
    for (int i = tid; i < total4; i += stride) n4[i] = z;
    for (int i = tid; i < N; i += stride) g_deg[i] = 0.f;
    if (blockIdx.x == 0 && threadIdx.x < DF) {
        g_sum[threadIdx.x] = 0.f;
        g_sumsq[threadIdx.x] = 0.f;
    }
}

// ---------------------------------------------------------------------------
// 2) Edge aggregation: one warp per edge, ONE vector red.128 per lane.
// ---------------------------------------------------------------------------
__global__ void agg_kernel(const float* __restrict__ feat,
                           const int* __restrict__ src,
                           const int* __restrict__ dst,
                           const float* __restrict__ ew,
                           int E) {
    int warp = (blockIdx.x * blockDim.x + threadIdx.x) >> 5;
    int lane = threadIdx.x & 31;
    if (warp >= E) return;
    int s = __ldg(&src[warp]);
    int d = __ldg(&dst[warp]);
    float w = __ldg(&ew[warp]);
    const float4 v = *reinterpret_cast<const float4*>(feat + (size_t)s * DF + lane * 4);
    float* nb = g_neigh + (size_t)d * DF + lane * 4;
    asm volatile("red.global.add.v4.f32 [%0], {%1, %2, %3, %4};"
                 :: "l"(nb), "f"(v.x * w), "f"(v.y * w), "f"(v.z * w), "f"(v.w * w)
                 : "memory");
    if (lane == 0) atomicAdd(&g_deg[d], w);
}

// ---------------------------------------------------------------------------
// 3) Fused dual GEMM + bias + ReLU + BN-stats, packed f32x2 FMA.
// ---------------------------------------------------------------------------
#define TM 64
#define WS_STRIDE 132
#define WS_FLOATS (256 * WS_STRIDE)
#define AS_FLOATS (TM * 256)
#define SMEM_FLOATS (WS_FLOATS + AS_FLOATS + TM)
#define SMEM_BYTES (SMEM_FLOATS * 4)

__device__ __forceinline__ unsigned long long pack2(float lo, float hi) {
    unsigned long long r;
    asm("mov.b64 %0, {%1, %2};" : "=l"(r) : "f"(lo), "f"(hi));
    return r;
}
__device__ __forceinline__ void unpack2(unsigned long long v, float& lo, float& hi) {
    asm("mov.b64 {%0, %1}, %2;" : "=f"(lo), "=f"(hi) : "l"(v));
}
__device__ __forceinline__ void fma_x2(unsigned long long& d,
                                       unsigned long long a,
                                       unsigned long long b) {
    asm("fma.rn.f32x2 %0, %1, %2, %0;" : "+l"(d) : "l"(a), "l"(b));
}

__global__ __launch_bounds__(256, 1)
void gemm_kernel(const float* __restrict__ feat,
                 const float* __restrict__ Wneigh,
                 const float* __restrict__ Wself,
                 const float* __restrict__ b_self,
                 const float* __restrict__ bias,
                 float* __restrict__ out,
                 int N) {
    extern __shared__ float sm[];
    float* Ws   = sm;                     // [256][WS_STRIDE], k-major
    float* As   = sm + WS_FLOATS;         // [TM][256], row-major
    float* sInv = As + AS_FLOATS;         // [TM]

    const int tid = threadIdx.x;
    const int ty = tid >> 5;              // 0..7  row group
    const int tx = tid & 31;              // 0..31 col group (cols tx*4..tx*4+3)

    for (int idx = tid; idx < DF * DF; idx += 256) {
        int o = idx >> 7;
        int d = idx & 127;
        Ws[d * WS_STRIDE + o]        = Wself[idx];
        Ws[(DF + d) * WS_STRIDE + o] = Wneigh[idx];
    }
    float bc[4];
#pragma unroll
    for (int c = 0; c < 4; c++)
        bc[c] = __ldg(&b_self[tx * 4 + c]) + __ldg(&bias[tx * 4 + c]);

    // per-thread BN stat accumulators for the 4 owned columns
    float st_s[4] = {0.f, 0.f, 0.f, 0.f};
    float st_q[4] = {0.f, 0.f, 0.f, 0.f};

    const int ntiles = (N + TM - 1) / TM;
    for (int tile = blockIdx.x; tile < ntiles; tile += gridDim.x) {
        const int row0 = tile * TM;
        const int rows = min(TM, N - row0);

        __syncthreads();
        if (tid < rows) sInv[tid] = 1.0f / (g_deg[row0 + tid] + 1e-8f);
        __syncthreads();

        for (int idx = tid; idx < rows * 256; idx += 256) {
            int r = idx >> 8;
            int k = idx & 255;
            float v;
            if (k < DF) v = feat[(size_t)(row0 + r) * DF + k];
            else        v = g_neigh[(size_t)(row0 + r) * DF + (k - DF)] * sInv[r];
            As[r * 256 + k] = v;
        }
        __syncthreads();

        unsigned long long acc[8][2];
#pragma unroll
        for (int j = 0; j < 8; j++) { acc[j][0] = 0ull; acc[j][1] = 0ull; }

        for (int k = 0; k < 256; k += 4) {
            float4 a4[8];
#pragma unroll
            for (int j = 0; j < 8; j++)
                a4[j] = *reinterpret_cast<const float4*>(&As[(ty + 8 * j) * 256 + k]);
#pragma unroll
            for (int kk = 0; kk < 4; kk++) {
                const ulonglong2 wp = *reinterpret_cast<const ulonglong2*>(
                    &Ws[(k + kk) * WS_STRIDE + tx * 4]);
#pragma unroll
                for (int j = 0; j < 8; j++) {
                    float a = (kk == 0) ? a4[j].x : (kk == 1) ? a4[j].y
                              : (kk == 2) ? a4[j].z : a4[j].w;
                    unsigned long long av = pack2(a, a);
                    fma_x2(acc[j][0], av, wp.x);
                    fma_x2(acc[j][1], av, wp.y);
                }
            }
        }

        // Epilogue: bias + ReLU, store, accumulate BN stats
#pragma unroll
        for (int j = 0; j < 8; j++) {
            int rl = ty + 8 * j;
            if (rl < rows) {
                float4 o4;
                unpack2(acc[j][0], o4.x, o4.y);
                unpack2(acc[j][1], o4.z, o4.w);
                o4.x = fmaxf(o4.x + bc[0], 0.f);
                o4.y = fmaxf(o4.y + bc[1], 0.f);
                o4.z = fmaxf(o4.z + bc[2], 0.f);
                o4.w = fmaxf(o4.w + bc[3], 0.f);
                *reinterpret_cast<float4*>(&out[(size_t)(row0 + rl) * DF + tx * 4]) = o4;
                st_s[0] += o4.x; st_q[0] += o4.x * o4.x;
                st_s[1] += o4.y; st_q[1] += o4.y * o4.y;
                st_s[2] += o4.z; st_q[2] += o4.z * o4.z;
                st_s[3] += o4.w; st_q[3] += o4.w * o4.w;
            }
        }
    }

    // Flush BN partial stats (256 distinct columns; contention negligible)
#pragma unroll
    for (int c = 0; c < 4; c++) {
        atomicAdd(&g_sum[tx * 4 + c], st_s[c]);
        atomicAdd(&g_sumsq[tx * 4 + c], st_q[c]);
    }
}

// ---------------------------------------------------------------------------
// 4) Finalize BN scale/shift
// ---------------------------------------------------------------------------
__global__ void finalize_kernel(const float* __restrict__ gamma,
                                const float* __restrict__ beta, int N) {
    int c = threadIdx.x;
    if (c < DF) {
        float invn = 1.0f / (float)N;
        float mu = g_sum[c] * invn;
        float var = g_sumsq[c] * invn - mu * mu;
        float rs = rsqrtf(var + 1e-5f);
        float sc = gamma[c] * rs;
        g_scale[c] = sc;
        g_shift[c] = beta[c] - mu * sc;
    }
}

// ---------------------------------------------------------------------------
// 5) Apply BN in place on out
// ---------------------------------------------------------------------------
__global__ void norm_kernel(float* __restrict__ out, int N) {
    int tid = blockIdx.x * blockDim.x + threadIdx.x;
    int stride = gridDim.x * blockDim.x;
    int total4 = N * (DF / 4);
    float4* o4 = reinterpret_cast<float4*>(out);
    for (int i = tid; i < total4; i += stride) {
        int col = (i & 31) * 4;
        float4 v = o4[i];
        v.x = v.x * g_scale[col + 0] + g_shift[col + 0];
        v.y = v.y * g_scale[col + 1] + g_shift[col + 1];
        v.z = v.z * g_scale[col + 2] + g_shift[col + 2];
        v.w = v.w * g_scale[col + 3] + g_shift[col + 3];
        o4[i] = v;
    }
}

// ---------------------------------------------------------------------------
// Launch
// ---------------------------------------------------------------------------
extern "C" void kernel_launch(void* const* d_in, const int* in_sizes, int n_in,
                              void* d_out, int out_size) {
    const float* feat   = (const float*)d_in[0];
    const int*   src    = (const int*)  d_in[1];
    const int*   dst    = (const int*)  d_in[2];
    const float* ew     = (const float*)d_in[3];
    const float* Wneigh = (const float*)d_in[4];
    const float* Wself  = (const float*)d_in[5];
    const float* b_self = (const float*)d_in[6];
    const float* bias   = (const float*)d_in[7];
    const float* gamma  = (const float*)d_in[8];
    const float* beta   = (const float*)d_in[9];
    float* out = (float*)d_out;

    const int N = in_sizes[0] / DF;
    const int E = in_sizes[1];

    cudaFuncSetAttribute(gemm_kernel,
                         cudaFuncAttributeMaxDynamicSharedMemorySize, SMEM_BYTES);

    zero_kernel<<<2048, 256>>>(N);
    agg_kernel<<<(E + 7) / 8, 256>>>(feat, src, dst, ew, E);
    gemm_kernel<<<148, 256, SMEM_BYTES>>>(feat, Wneigh, Wself, b_self, bias, out, N);
    finalize_kernel<<<1, 128>>>(gamma, beta, N);
    norm_kernel<<<2048, 256>>>(out, N);
}

// round 6
// speedup vs baseline: 1.8307x; 1.1482x over previous
#include <cuda_runtime.h>

#define NMAX 50000
#define EMAX 800000
#define DF   128

__device__ float g_neigh[NMAX * DF];      // normalized neighbor means
__device__ int   g_cnt[NMAX];             // per-dst edge counts
__device__ int   g_off[NMAX + 1];         // CSR offsets
__device__ int   g_cur[NMAX];             // scatter cursors
__device__ int   g_esrc[EMAX];            // CSR-ordered src ids
__device__ float g_ew[EMAX];              // CSR-ordered edge weights
__device__ float g_sum[DF];
__device__ float g_sumsq[DF];

// ---------------------------------------------------------------------------
// 1) Zero counters + BN stats (no more 25.6MB neigh zeroing!)
// ---------------------------------------------------------------------------
__global__ void zero_kernel(int N) {
    int tid = blockIdx.x * blockDim.x + threadIdx.x;
    int stride = gridDim.x * blockDim.x;
    for (int i = tid; i < N; i += stride) g_cnt[i] = 0;
    if (blockIdx.x == 0 && threadIdx.x < DF) {
        g_sum[threadIdx.x] = 0.f;
        g_sumsq[threadIdx.x] = 0.f;
    }
}

// ---------------------------------------------------------------------------
// 2) Histogram of dst
// ---------------------------------------------------------------------------
__global__ void hist_kernel(const int* __restrict__ dst, int E) {
    int i = blockIdx.x * blockDim.x + threadIdx.x;
    if (i < E) atomicAdd(&g_cnt[dst[i]], 1);
}

// ---------------------------------------------------------------------------
// 3) Exclusive scan over counts (single block, warp-shfl two-level scan)
// ---------------------------------------------------------------------------
__global__ __launch_bounds__(1024, 1)
void scan_kernel(int N) {
    __shared__ int warp_sums[32];
    __shared__ int s_carry;
    const int tid = threadIdx.x;
    const int lane = tid & 31, wid = tid >> 5;
    if (tid == 0) s_carry = 0;
    __syncthreads();
    for (int base = 0; base < N; base += 1024) {
        int i = base + tid;
        int v = (i < N) ? g_cnt[i] : 0;
        int x = v;
#pragma unroll
        for (int o = 1; o < 32; o <<= 1) {
            int y = __shfl_up_sync(0xFFFFFFFFu, x, o);
            if (lane >= o) x += y;
        }
        if (lane == 31) warp_sums[wid] = x;
        __syncthreads();
        if (wid == 0) {
            int s = warp_sums[lane];
#pragma unroll
            for (int o = 1; o < 32; o <<= 1) {
                int y = __shfl_up_sync(0xFFFFFFFFu, s, o);
                if (lane >= o) s += y;
            }
            warp_sums[lane] = s;
        }
        __syncthreads();
        int warp_excl = (wid == 0) ? 0 : warp_sums[wid - 1];
        int excl = s_carry + warp_excl + x - v;
        if (i < N) { g_off[i] = excl; g_cur[i] = excl; }
        int chunk_total = warp_sums[31];
        __syncthreads();
        if (tid == 0) s_carry += chunk_total;
        __syncthreads();
    }
    if (tid == 0) g_off[N] = s_carry;
}

// ---------------------------------------------------------------------------
// 4) Scatter edges into CSR order
// ---------------------------------------------------------------------------
__global__ void scatter_kernel(const int* __restrict__ src,
                               const int* __restrict__ dst,
                               const float* __restrict__ ew,
                               int E) {
    int i = blockIdx.x * blockDim.x + threadIdx.x;
    if (i < E) {
        int d = dst[i];
        int pos = atomicAdd(&g_cur[d], 1);
        g_esrc[pos] = src[i];
        g_ew[pos] = ew[i];
    }
}

// ---------------------------------------------------------------------------
// 5) Gather-aggregate: one warp per node, register accumulation, no atomics.
//    Writes already-normalized neighbor mean.
// ---------------------------------------------------------------------------
__global__ void agg_kernel(const float* __restrict__ feat, int N) {
    int node = (blockIdx.x * blockDim.x + threadIdx.x) >> 5;
    int lane = threadIdx.x & 31;
    if (node >= N) return;
    int beg = g_off[node];
    int end = g_off[node + 1];
    float4 acc = make_float4(0.f, 0.f, 0.f, 0.f);
    float deg = 0.f;
    for (int e = beg; e < end; e++) {
        int s = __ldg(&g_esrc[e]);          // uniform across warp -> broadcast
        float w = __ldg(&g_ew[e]);
        const float4 v = *reinterpret_cast<const float4*>(
            feat + (size_t)s * DF + lane * 4);
        acc.x = fmaf(v.x, w, acc.x);
        acc.y = fmaf(v.y, w, acc.y);
        acc.z = fmaf(v.z, w, acc.z);
        acc.w = fmaf(v.w, w, acc.w);
        deg += w;
    }
    float inv = 1.0f / (deg + 1e-8f);
    acc.x *= inv; acc.y *= inv; acc.z *= inv; acc.w *= inv;
    *reinterpret_cast<float4*>(g_neigh + (size_t)node * DF + lane * 4) = acc;
}

// ---------------------------------------------------------------------------
// 6) Fused dual GEMM + bias + ReLU + BN-stats, packed f32x2 FMA.
// ---------------------------------------------------------------------------
#define TM 64
#define WS_STRIDE 132
#define WS_FLOATS (256 * WS_STRIDE)
#define AS_FLOATS (TM * 256)
#define SMEM_FLOATS (WS_FLOATS + AS_FLOATS)
#define SMEM_BYTES (SMEM_FLOATS * 4)

__device__ __forceinline__ unsigned long long pack2(float lo, float hi) {
    unsigned long long r;
    asm("mov.b64 %0, {%1, %2};" : "=l"(r) : "f"(lo), "f"(hi));
    return r;
}
__device__ __forceinline__ void unpack2(unsigned long long v, float& lo, float& hi) {
    asm("mov.b64 {%0, %1}, %2;" : "=f"(lo), "=f"(hi) : "l"(v));
}
__device__ __forceinline__ void fma_x2(unsigned long long& d,
                                       unsigned long long a,
                                       unsigned long long b) {
    asm("fma.rn.f32x2 %0, %1, %2, %0;" : "+l"(d) : "l"(a), "l"(b));
}

__global__ __launch_bounds__(256, 1)
void gemm_kernel(const float* __restrict__ feat,
                 const float* __restrict__ Wneigh,
                 const float* __restrict__ Wself,
                 const float* __restrict__ b_self,
                 const float* __restrict__ bias,
                 float* __restrict__ out,
                 int N) {
    extern __shared__ float sm[];
    float* Ws = sm;                       // [256][WS_STRIDE], k-major
    float* As = sm + WS_FLOATS;           // [TM][256], row-major

    const int tid = threadIdx.x;
    const int ty = tid >> 5;              // 0..7  row group
    const int tx = tid & 31;              // 0..31 col group

    for (int idx = tid; idx < DF * DF; idx += 256) {
        int o = idx >> 7;
        int d = idx & 127;
        Ws[d * WS_STRIDE + o]        = Wself[idx];
        Ws[(DF + d) * WS_STRIDE + o] = Wneigh[idx];
    }
    float bc[4];
#pragma unroll
    for (int c = 0; c < 4; c++)
        bc[c] = __ldg(&b_self[tx * 4 + c]) + __ldg(&bias[tx * 4 + c]);

    float st_s[4] = {0.f, 0.f, 0.f, 0.f};
    float st_q[4] = {0.f, 0.f, 0.f, 0.f};

    const int ntiles = (N + TM - 1) / TM;
    for (int tile = blockIdx.x; tile < ntiles; tile += gridDim.x) {
        const int row0 = tile * TM;
        const int rows = min(TM, N - row0);

        __syncthreads();
        for (int idx = tid; idx < rows * 256; idx += 256) {
            int r = idx >> 8;
            int k = idx & 255;
            float v;
            if (k < DF) v = feat[(size_t)(row0 + r) * DF + k];
            else        v = g_neigh[(size_t)(row0 + r) * DF + (k - DF)];
            As[r * 256 + k] = v;
        }
        __syncthreads();

        unsigned long long acc[8][2];
#pragma unroll
        for (int j = 0; j < 8; j++) { acc[j][0] = 0ull; acc[j][1] = 0ull; }

        for (int k = 0; k < 256; k += 4) {
            float4 a4[8];
#pragma unroll
            for (int j = 0; j < 8; j++)
                a4[j] = *reinterpret_cast<const float4*>(&As[(ty + 8 * j) * 256 + k]);
#pragma unroll
            for (int kk = 0; kk < 4; kk++) {
                const ulonglong2 wp = *reinterpret_cast<const ulonglong2*>(
                    &Ws[(k + kk) * WS_STRIDE + tx * 4]);
#pragma unroll
                for (int j = 0; j < 8; j++) {
                    float a = (kk == 0) ? a4[j].x : (kk == 1) ? a4[j].y
                              : (kk == 2) ? a4[j].z : a4[j].w;
                    unsigned long long av = pack2(a, a);
                    fma_x2(acc[j][0], av, wp.x);
                    fma_x2(acc[j][1], av, wp.y);
                }
            }
        }

#pragma unroll
        for (int j = 0; j < 8; j++) {
            int rl = ty + 8 * j;
            if (rl < rows) {
                float4 o4;
                unpack2(acc[j][0], o4.x, o4.y);
                unpack2(acc[j][1], o4.z, o4.w);
                o4.x = fmaxf(o4.x + bc[0], 0.f);
                o4.y = fmaxf(o4.y + bc[1], 0.f);
                o4.z = fmaxf(o4.z + bc[2], 0.f);
                o4.w = fmaxf(o4.w + bc[3], 0.f);
                *reinterpret_cast<float4*>(&out[(size_t)(row0 + rl) * DF + tx * 4]) = o4;
                st_s[0] += o4.x; st_q[0] += o4.x * o4.x;
                st_s[1] += o4.y; st_q[1] += o4.y * o4.y;
                st_s[2] += o4.z; st_q[2] += o4.z * o4.z;
                st_s[3] += o4.w; st_q[3] += o4.w * o4.w;
            }
        }
    }

#pragma unroll
    for (int c = 0; c < 4; c++) {
        atomicAdd(&g_sum[tx * 4 + c], st_s[c]);
        atomicAdd(&g_sumsq[tx * 4 + c], st_q[c]);
    }
}

// ---------------------------------------------------------------------------
// 7) Apply BN in place (finalize fused: columns are loop-invariant per thread)
// ---------------------------------------------------------------------------
__global__ void norm_kernel(float* __restrict__ out,
                            const float* __restrict__ gamma,
                            const float* __restrict__ beta,
                            int N) {
    int tid = blockIdx.x * blockDim.x + threadIdx.x;
    int stride = gridDim.x * blockDim.x;   // multiple of 32 -> column fixed
    int colbase = (tid & 31) * 4;
    float invn = 1.0f / (float)N;
    float sc[4], sh[4];
#pragma unroll
    for (int c = 0; c < 4; c++) {
        int col = colbase + c;
        float mu = g_sum[col] * invn;
        float var = g_sumsq[col] * invn - mu * mu;
        float rs = rsqrtf(var + 1e-5f);
        float s = gamma[col] * rs;
        sc[c] = s;
        sh[c] = beta[col] - mu * s;
    }
    int total4 = N * (DF / 4);
    float4* o4 = reinterpret_cast<float4*>(out);
    for (int i = tid; i < total4; i += stride) {
        float4 v = o4[i];
        v.x = v.x * sc[0] + sh[0];
        v.y = v.y * sc[1] + sh[1];
        v.z = v.z * sc[2] + sh[2];
        v.w = v.w * sc[3] + sh[3];
        o4[i] = v;
    }
}

// ---------------------------------------------------------------------------
// Launch
// ---------------------------------------------------------------------------
extern "C" void kernel_launch(void* const* d_in, const int* in_sizes, int n_in,
                              void* d_out, int out_size) {
    const float* feat   = (const float*)d_in[0];
    const int*   src    = (const int*)  d_in[1];
    const int*   dst    = (const int*)  d_in[2];
    const float* ew     = (const float*)d_in[3];
    const float* Wneigh = (const float*)d_in[4];
    const float* Wself  = (const float*)d_in[5];
    const float* b_self = (const float*)d_in[6];
    const float* bias   = (const float*)d_in[7];
    const float* gamma  = (const float*)d_in[8];
    const float* beta   = (const float*)d_in[9];
    float* out = (float*)d_out;

    const int N = in_sizes[0] / DF;
    const int E = in_sizes[1];

    cudaFuncSetAttribute(gemm_kernel,
                         cudaFuncAttributeMaxDynamicSharedMemorySize, SMEM_BYTES);

    zero_kernel<<<64, 256>>>(N);
    hist_kernel<<<(E + 255) / 256, 256>>>(dst, E);
    scan_kernel<<<1, 1024>>>(N);
    scatter_kernel<<<(E + 255) / 256, 256>>>(src, dst, ew, E);
    agg_kernel<<<(N * 32 + 255) / 256, 256>>>(feat, N);
    gemm_kernel<<<148, 256, SMEM_BYTES>>>(feat, Wneigh, Wself, b_self, bias, out, N);
    norm_kernel<<<1024, 256>>>(out, gamma, beta, N);
}

// round 7
// speedup vs baseline: 1.9036x; 1.0398x over previous
#include <cuda_runtime.h>

#define NMAX 50000
#define NPAD 53248          // padded for int4 scan loads
#define EMAX 800000
#define DF   128

__device__ float g_neigh[NMAX * DF];      // normalized neighbor means
__device__ int   g_cnt[NPAD];             // per-dst edge counts (padded, zeroed)
__device__ int   g_off[NMAX + 4];         // CSR offsets
__device__ int   g_cur[NMAX + 4];         // scatter cursors
__device__ int2  g_edge[EMAX];            // CSR-ordered (src, bitcast(w))
__device__ float g_sum[DF];
__device__ float g_sumsq[DF];
__device__ unsigned g_bar;                // grid barrier counter

// ---------------------------------------------------------------------------
// 1) Zero counters + BN stats + barrier
// ---------------------------------------------------------------------------
__global__ void zero_kernel() {
    int tid = blockIdx.x * blockDim.x + threadIdx.x;
    int stride = gridDim.x * blockDim.x;
    for (int i = tid; i < NPAD; i += stride) g_cnt[i] = 0;
    if (blockIdx.x == 0) {
        if (threadIdx.x < DF) {
            g_sum[threadIdx.x] = 0.f;
            g_sumsq[threadIdx.x] = 0.f;
        }
        if (threadIdx.x == 0) g_bar = 0;
    }
}

// ---------------------------------------------------------------------------
// 2) Histogram of dst (vectorized load)
// ---------------------------------------------------------------------------
__global__ void hist_kernel(const int* __restrict__ dst, int E) {
    int i4 = (blockIdx.x * blockDim.x + threadIdx.x) * 4;
    if (i4 + 3 < E) {
        int4 d = *reinterpret_cast<const int4*>(dst + i4);
        atomicAdd(&g_cnt[d.x], 1);
        atomicAdd(&g_cnt[d.y], 1);
        atomicAdd(&g_cnt[d.z], 1);
        atomicAdd(&g_cnt[d.w], 1);
    } else {
        for (int i = i4; i < E; i++) atomicAdd(&g_cnt[dst[i]], 1);
    }
}

// ---------------------------------------------------------------------------
// 3) Exclusive scan (single block, 4 elems/thread, warp-shfl two-level)
// ---------------------------------------------------------------------------
__global__ __launch_bounds__(1024, 1)
void scan_kernel(int N) {
    __shared__ int wsum[32];
    __shared__ int s_carry;
    const int tid = threadIdx.x;
    const int lane = tid & 31, wid = tid >> 5;
    if (tid == 0) s_carry = 0;
    __syncthreads();
    const int CH = 4096;
    for (int base = 0; base < N; base += CH) {
        int i0 = base + tid * 4;
        int4 v = *reinterpret_cast<const int4*>(&g_cnt[i0]);  // padded & zeroed
        int s0 = v.x, s1 = s0 + v.y, s2 = s1 + v.z, s3 = s2 + v.w;
        int x = s3;
#pragma unroll
        for (int o = 1; o < 32; o <<= 1) {
            int y = __shfl_up_sync(0xFFFFFFFFu, x, o);
            if (lane >= o) x += y;
        }
        if (lane == 31) wsum[wid] = x;
        __syncthreads();
        if (wid == 0) {
            int s = wsum[lane];
#pragma unroll
            for (int o = 1; o < 32; o <<= 1) {
                int y = __shfl_up_sync(0xFFFFFFFFu, s, o);
                if (lane >= o) s += y;
            }
            wsum[lane] = s;
        }
        __syncthreads();
        int we = (wid == 0) ? 0 : wsum[wid - 1];
        int excl = s_carry + we + x - s3;
        if (i0 < N) {   // N % 4 == 0, so full int4 is in range
            int4 off = make_int4(excl, excl + s0, excl + s1, excl + s2);
            *reinterpret_cast<int4*>(&g_off[i0]) = off;
            *reinterpret_cast<int4*>(&g_cur[i0]) = off;
        }
        int chunk_total = wsum[31];
        __syncthreads();
        if (tid == 0) s_carry += chunk_total;
        __syncthreads();
    }
    if (tid == 0) g_off[N] = s_carry;
}

// ---------------------------------------------------------------------------
// 4) Scatter edges into CSR order, single int2 store
// ---------------------------------------------------------------------------
__global__ void scatter_kernel(const int* __restrict__ src,
                               const int* __restrict__ dst,
                               const float* __restrict__ ew,
                               int E) {
    int i = blockIdx.x * blockDim.x + threadIdx.x;
    if (i < E) {
        int d = dst[i];
        int pos = atomicAdd(&g_cur[d], 1);
        g_edge[pos] = make_int2(src[i], __float_as_int(ew[i]));
    }
}

// ---------------------------------------------------------------------------
// 5) Gather-aggregate: one warp per node, no atomics, normalized output.
// ---------------------------------------------------------------------------
__global__ void agg_kernel(const float* __restrict__ feat, int N) {
    int node = (blockIdx.x * blockDim.x + threadIdx.x) >> 5;
    int lane = threadIdx.x & 31;
    if (node >= N) return;
    int beg = g_off[node];
    int end = g_off[node + 1];
    float4 acc = make_float4(0.f, 0.f, 0.f, 0.f);
    float deg = 0.f;
    for (int e = beg; e < end; e++) {
        int2 ed = __ldg(&g_edge[e]);        // uniform across warp -> broadcast
        float w = __int_as_float(ed.y);
        const float4 v = *reinterpret_cast<const float4*>(
            feat + (size_t)ed.x * DF + lane * 4);
        acc.x = fmaf(v.x, w, acc.x);
        acc.y = fmaf(v.y, w, acc.y);
        acc.z = fmaf(v.z, w, acc.z);
        acc.w = fmaf(v.w, w, acc.w);
        deg += w;
    }
    float inv = 1.0f / (deg + 1e-8f);
    acc.x *= inv; acc.y *= inv; acc.z *= inv; acc.w *= inv;
    *reinterpret_cast<float4*>(g_neigh + (size_t)node * DF + lane * 4) = acc;
}

// ---------------------------------------------------------------------------
// 6) Persistent fused dual GEMM + bias + ReLU + BN stats + grid barrier + BN
// ---------------------------------------------------------------------------
#define TM 64
#define WS_STRIDE 132
#define WS_FLOATS (256 * WS_STRIDE)
#define AS_FLOATS (TM * 256)
#define SMEM_FLOATS (WS_FLOATS + AS_FLOATS)
#define SMEM_BYTES (SMEM_FLOATS * 4)
#define GRID_GEMM 148

__device__ __forceinline__ unsigned long long pack2(float lo, float hi) {
    unsigned long long r;
    asm("mov.b64 %0, {%1, %2};" : "=l"(r) : "f"(lo), "f"(hi));
    return r;
}
__device__ __forceinline__ void unpack2(unsigned long long v, float& lo, float& hi) {
    asm("mov.b64 {%0, %1}, %2;" : "=f"(lo), "=f"(hi) : "l"(v));
}
__device__ __forceinline__ void fma_x2(unsigned long long& d,
                                       unsigned long long a,
                                       unsigned long long b) {
    asm("fma.rn.f32x2 %0, %1, %2, %0;" : "+l"(d) : "l"(a), "l"(b));
}

__global__ __launch_bounds__(256, 1)
void gemm_kernel(const float* __restrict__ feat,
                 const float* __restrict__ Wneigh,
                 const float* __restrict__ Wself,
                 const float* __restrict__ b_self,
                 const float* __restrict__ bias,
                 const float* __restrict__ gamma,
                 const float* __restrict__ beta,
                 float* __restrict__ out,
                 int N) {
    extern __shared__ float sm[];
    float* Ws = sm;                       // [256][WS_STRIDE], k-major
    float* As = sm + WS_FLOATS;           // [TM][256], row-major

    const int tid = threadIdx.x;
    const int ty = tid >> 5;              // 0..7  row group
    const int tx = tid & 31;              // 0..31 col group

    for (int idx = tid; idx < DF * DF; idx += 256) {
        int o = idx >> 7;
        int d = idx & 127;
        Ws[d * WS_STRIDE + o]        = Wself[idx];
        Ws[(DF + d) * WS_STRIDE + o] = Wneigh[idx];
    }
    float bc[4];
#pragma unroll
    for (int c = 0; c < 4; c++)
        bc[c] = __ldg(&b_self[tx * 4 + c]) + __ldg(&bias[tx * 4 + c]);

    float st_s[4] = {0.f, 0.f, 0.f, 0.f};
    float st_q[4] = {0.f, 0.f, 0.f, 0.f};

    const int ntiles = (N + TM - 1) / TM;
    for (int tile = blockIdx.x; tile < ntiles; tile += gridDim.x) {
        const int row0 = tile * TM;
        const int rows = min(TM, N - row0);

        __syncthreads();
        // A-tile fill, float4-vectorized: 64 float4 per row (32 feat + 32 neigh)
        for (int idx = tid; idx < rows * 64; idx += 256) {
            int r = idx >> 6;
            int k4 = idx & 63;
            float4 v;
            if (k4 < 32)
                v = *reinterpret_cast<const float4*>(
                        feat + (size_t)(row0 + r) * DF + k4 * 4);
            else
                v = *reinterpret_cast<const float4*>(
                        g_neigh + (size_t)(row0 + r) * DF + (k4 - 32) * 4);
            *reinterpret_cast<float4*>(&As[r * 256 + k4 * 4]) = v;
        }
        __syncthreads();

        unsigned long long acc[8][2];
#pragma unroll
        for (int j = 0; j < 8; j++) { acc[j][0] = 0ull; acc[j][1] = 0ull; }

        for (int k = 0; k < 256; k += 4) {
            float4 a4[8];
#pragma unroll
            for (int j = 0; j < 8; j++)
                a4[j] = *reinterpret_cast<const float4*>(&As[(ty + 8 * j) * 256 + k]);
#pragma unroll
            for (int kk = 0; kk < 4; kk++) {
                const ulonglong2 wp = *reinterpret_cast<const ulonglong2*>(
                    &Ws[(k + kk) * WS_STRIDE + tx * 4]);
#pragma unroll
                for (int j = 0; j < 8; j++) {
                    float a = (kk == 0) ? a4[j].x : (kk == 1) ? a4[j].y
                              : (kk == 2) ? a4[j].z : a4[j].w;
                    unsigned long long av = pack2(a, a);
                    fma_x2(acc[j][0], av, wp.x);
                    fma_x2(acc[j][1], av, wp.y);
                }
            }
        }

#pragma unroll
        for (int j = 0; j < 8; j++) {
            int rl = ty + 8 * j;
            if (rl < rows) {
                float4 o4;
                unpack2(acc[j][0], o4.x, o4.y);
                unpack2(acc[j][1], o4.z, o4.w);
                o4.x = fmaxf(o4.x + bc[0], 0.f);
                o4.y = fmaxf(o4.y + bc[1], 0.f);
                o4.z = fmaxf(o4.z + bc[2], 0.f);
                o4.w = fmaxf(o4.w + bc[3], 0.f);
                *reinterpret_cast<float4*>(&out[(size_t)(row0 + rl) * DF + tx * 4]) = o4;
                st_s[0] += o4.x; st_q[0] += o4.x * o4.x;
                st_s[1] += o4.y; st_q[1] += o4.y * o4.y;
                st_s[2] += o4.z; st_q[2] += o4.z * o4.z;
                st_s[3] += o4.w; st_q[3] += o4.w * o4.w;
            }
        }
    }

    // Flush BN partial stats
#pragma unroll
    for (int c = 0; c < 4; c++) {
        atomicAdd(&g_sum[tx * 4 + c], st_s[c]);
        atomicAdd(&g_sumsq[tx * 4 + c], st_q[c]);
    }

    // ---- Grid-wide barrier (all 148 blocks resident: 1 block/SM) ----
    __threadfence();
    __syncthreads();
    if (tid == 0) {
        atomicAdd(&g_bar, 1u);
        while (atomicAdd(&g_bar, 0u) < (unsigned)gridDim.x) __nanosleep(64);
    }
    __syncthreads();
    __threadfence();

    // ---- BN normalize (re-read own tiles; L2-warm) ----
    float invn = 1.0f / (float)N;
    float sc[4], sh[4];
#pragma unroll
    for (int c = 0; c < 4; c++) {
        int col = tx * 4 + c;
        float mu = __ldcg(&g_sum[col]) * invn;
        float var = __ldcg(&g_sumsq[col]) * invn - mu * mu;
        float rs = rsqrtf(var + 1e-5f);
        float s = gamma[col] * rs;
        sc[c] = s;
        sh[c] = beta[col] - mu * s;
    }
    for (int tile = blockIdx.x; tile < ntiles; tile += gridDim.x) {
        const int row0 = tile * TM;
        const int rows = min(TM, N - row0);
#pragma unroll
        for (int j = 0; j < 8; j++) {
            int rl = ty + 8 * j;
            if (rl < rows) {
                float4* p = reinterpret_cast<float4*>(
                    &out[(size_t)(row0 + rl) * DF + tx * 4]);
                float4 v = *p;
                v.x = v.x * sc[0] + sh[0];
                v.y = v.y * sc[1] + sh[1];
                v.z = v.z * sc[2] + sh[2];
                v.w = v.w * sc[3] + sh[3];
                *p = v;
            }
        }
    }
}

// ---------------------------------------------------------------------------
// Launch
// ---------------------------------------------------------------------------
extern "C" void kernel_launch(void* const* d_in, const int* in_sizes, int n_in,
                              void* d_out, int out_size) {
    const float* feat   = (const float*)d_in[0];
    const int*   src    = (const int*)  d_in[1];
    const int*   dst    = (const int*)  d_in[2];
    const float* ew     = (const float*)d_in[3];
    const float* Wneigh = (const float*)d_in[4];
    const float* Wself  = (const float*)d_in[5];
    const float* b_self = (const float*)d_in[6];
    const float* bias   = (const float*)d_in[7];
    const float* gamma  = (const float*)d_in[8];
    const float* beta   = (const float*)d_in[9];
    float* out = (float*)d_out;

    const int N = in_sizes[0] / DF;
    const int E = in_sizes[1];

    cudaFuncSetAttribute(gemm_kernel,
                         cudaFuncAttributeMaxDynamicSharedMemorySize, SMEM_BYTES);

    zero_kernel<<<64, 256>>>();
    hist_kernel<<<(E / 4 + 255) / 256, 256>>>(dst, E);
    scan_kernel<<<1, 1024>>>(N);
    scatter_kernel<<<(E + 255) / 256, 256>>>(src, dst, ew, E);
    agg_kernel<<<(N * 32 + 255) / 256, 256>>>(feat, N);
    gemm_kernel<<<GRID_GEMM, 256, SMEM_BYTES>>>(feat, Wneigh, Wself, b_self, bias,
                                                gamma, beta, out, N);
}

// round 13
// speedup vs baseline: 2.3035x; 1.2101x over previous
#include <cuda_runtime.h>
#include <cuda_bf16.h>
#include <cstdint>

#define NMAX 50000
#define NPAD 53248
#define EMAX 800000
#define DF   128

__device__ float g_neigh[NMAX * DF];
__device__ int   g_cnt[NPAD];
__device__ int   g_off[NMAX + 4];
__device__ int   g_cur[NMAX + 4];
__device__ int2  g_edge[EMAX];
__device__ float g_sum[DF];
__device__ float g_sumsq[DF];
__device__ unsigned g_bar;

// ===========================================================================
// 1) Zero counters + BN stats + barrier
// ===========================================================================
__global__ void zero_kernel() {
    int tid = blockIdx.x * blockDim.x + threadIdx.x;
    int stride = gridDim.x * blockDim.x;
    for (int i = tid; i < NPAD; i += stride) g_cnt[i] = 0;
    if (blockIdx.x == 0) {
        if (threadIdx.x < DF) {
            g_sum[threadIdx.x] = 0.f;
            g_sumsq[threadIdx.x] = 0.f;
        }
        if (threadIdx.x == 0) g_bar = 0;
    }
}

// ===========================================================================
// 2) Histogram of dst
// ===========================================================================
__global__ void hist_kernel(const int* __restrict__ dst, int E) {
    int i4 = (blockIdx.x * blockDim.x + threadIdx.x) * 4;
    if (i4 + 3 < E) {
        int4 d = *reinterpret_cast<const int4*>(dst + i4);
        atomicAdd(&g_cnt[d.x], 1);
        atomicAdd(&g_cnt[d.y], 1);
        atomicAdd(&g_cnt[d.z], 1);
        atomicAdd(&g_cnt[d.w], 1);
    } else {
        for (int i = i4; i < E; i++) atomicAdd(&g_cnt[dst[i]], 1);
    }
}

// ===========================================================================
// 3) Exclusive scan
// ===========================================================================
__global__ __launch_bounds__(1024, 1)
void scan_kernel(int N) {
    __shared__ int wsum[32];
    __shared__ int s_carry;
    const int tid = threadIdx.x;
    const int lane = tid & 31, wid = tid >> 5;
    if (tid == 0) s_carry = 0;
    __syncthreads();
    const int CH = 4096;
    for (int base = 0; base < N; base += CH) {
        int i0 = base + tid * 4;
        int4 v = *reinterpret_cast<const int4*>(&g_cnt[i0]);
        int s0 = v.x, s1 = s0 + v.y, s2 = s1 + v.z, s3 = s2 + v.w;
        int x = s3;
#pragma unroll
        for (int o = 1; o < 32; o <<= 1) {
            int y = __shfl_up_sync(0xFFFFFFFFu, x, o);
            if (lane >= o) x += y;
        }
        if (lane == 31) wsum[wid] = x;
        __syncthreads();
        if (wid == 0) {
            int s = wsum[lane];
#pragma unroll
            for (int o = 1; o < 32; o <<= 1) {
                int y = __shfl_up_sync(0xFFFFFFFFu, s, o);
                if (lane >= o) s += y;
            }
            wsum[lane] = s;
        }
        __syncthreads();
        int we = (wid == 0) ? 0 : wsum[wid - 1];
        int excl = s_carry + we + x - s3;
        if (i0 < N) {
            int4 off = make_int4(excl, excl + s0, excl + s1, excl + s2);
            *reinterpret_cast<int4*>(&g_off[i0]) = off;
            *reinterpret_cast<int4*>(&g_cur[i0]) = off;
        }
        int chunk_total = wsum[31];
        __syncthreads();
        if (tid == 0) s_carry += chunk_total;
        __syncthreads();
    }
    if (tid == 0) g_off[N] = s_carry;
}

// ===========================================================================
// 4) Scatter edges into CSR order
// ===========================================================================
__global__ void scatter_kernel(const int* __restrict__ src,
                               const int* __restrict__ dst,
                               const float* __restrict__ ew,
                               int E) {
    int i = blockIdx.x * blockDim.x + threadIdx.x;
    if (i < E) {
        int d = dst[i];
        int pos = atomicAdd(&g_cur[d], 1);
        g_edge[pos] = make_int2(src[i], __float_as_int(ew[i]));
    }
}

// ===========================================================================
// 5) Gather-aggregate: one warp per node
// ===========================================================================
__global__ void agg_kernel(const float* __restrict__ feat, int N) {
    int node = (blockIdx.x * blockDim.x + threadIdx.x) >> 5;
    int lane = threadIdx.x & 31;
    if (node >= N) return;
    int beg = g_off[node];
    int end = g_off[node + 1];
    float4 acc = make_float4(0.f, 0.f, 0.f, 0.f);
    float deg = 0.f;
    for (int e = beg; e < end; e++) {
        int2 ed = __ldg(&g_edge[e]);
        float w = __int_as_float(ed.y);
        const float4 v = *reinterpret_cast<const float4*>(
            feat + (size_t)ed.x * DF + lane * 4);
        acc.x = fmaf(v.x, w, acc.x);
        acc.y = fmaf(v.y, w, acc.y);
        acc.z = fmaf(v.z, w, acc.z);
        acc.w = fmaf(v.w, w, acc.w);
        deg += w;
    }
    float inv = 1.0f / (deg + 1e-8f);
    acc.x *= inv; acc.y *= inv; acc.z *= inv; acc.w *= inv;
    *reinterpret_cast<float4*>(g_neigh + (size_t)node * DF + lane * 4) = acc;
}

// ===========================================================================
// 6) mma.sync split-bf16 GEMM + bias + ReLU + BN stats + barrier + BN
//    Block tile 64 rows x 128 cols; 8 warps = 2(m) x 4(n); warp tile 32x32.
//    3 passes: Ahi*Whi + Ahi*Wlo + Alo*Whi, fp32 accumulate.
// ===========================================================================
#define TILE_M 64
#define GRID_GEMM 148
// SMEM byte offsets (dynamic)
#define SM_WHI  0
#define SM_WLO  65536
#define SM_AHI  131072
#define SM_ALO  163840
#define SM_BC   196608
#define SM_SSUM 197120
#define SM_SSQ  197632
#define SMEM_GEMM_BYTES 198272

__device__ __forceinline__ uint32_t smem_u32(const void* p) {
    uint32_t a;
    asm("{ .reg .u64 t; cvta.to.shared.u64 t, %1; cvt.u32.u64 %0, t; }"
        : "=r"(a) : "l"(p));
    return a;
}
__device__ __forceinline__ void ldsm4(uint32_t& r0, uint32_t& r1,
                                      uint32_t& r2, uint32_t& r3, uint32_t addr) {
    asm volatile("ldmatrix.sync.aligned.m8n8.x4.shared.b16 {%0,%1,%2,%3}, [%4];"
                 : "=r"(r0), "=r"(r1), "=r"(r2), "=r"(r3) : "r"(addr));
}
__device__ __forceinline__ void mma16816(float* d, uint32_t a0, uint32_t a1,
                                         uint32_t a2, uint32_t a3,
                                         uint32_t b0, uint32_t b1) {
    asm volatile(
        "mma.sync.aligned.m16n8k16.row.col.f32.bf16.bf16.f32 "
        "{%0,%1,%2,%3}, {%4,%5,%6,%7}, {%8,%9}, {%0,%1,%2,%3};"
        : "+f"(d[0]), "+f"(d[1]), "+f"(d[2]), "+f"(d[3])
        : "r"(a0), "r"(a1), "r"(a2), "r"(a3), "r"(b0), "r"(b1));
}
// convert 8 fp32 -> 8 bf16 hi + 8 bf16 lo (packed as uint4 each)
__device__ __forceinline__ void cvt8(const float* f, uint4& hi, uint4& lo) {
    uint32_t h[4], l[4];
#pragma unroll
    for (int i = 0; i < 4; i++) {
        __nv_bfloat16 h0 = __float2bfloat16_rn(f[2 * i]);
        __nv_bfloat16 h1 = __float2bfloat16_rn(f[2 * i + 1]);
        h[i] = (uint32_t)__bfloat16_as_ushort(h0)
             | ((uint32_t)__bfloat16_as_ushort(h1) << 16);
        __nv_bfloat16 l0 = __float2bfloat16_rn(f[2 * i] - __bfloat162float(h0));
        __nv_bfloat16 l1 = __float2bfloat16_rn(f[2 * i + 1] - __bfloat162float(h1));
        l[i] = (uint32_t)__bfloat16_as_ushort(l0)
             | ((uint32_t)__bfloat16_as_ushort(l1) << 16);
    }
    hi = make_uint4(h[0], h[1], h[2], h[3]);
    lo = make_uint4(l[0], l[1], l[2], l[3]);
}

__global__ __launch_bounds__(256, 1)
void gemm_kernel(const float* __restrict__ feat,
                 const float* __restrict__ Wneigh,
                 const float* __restrict__ Wself,
                 const float* __restrict__ b_self,
                 const float* __restrict__ bias,
                 const float* __restrict__ gamma,
                 const float* __restrict__ beta,
                 float* __restrict__ out,
                 int N) {
    extern __shared__ char sm[];
    float* s_bc   = reinterpret_cast<float*>(sm + SM_BC);
    float* s_ssum = reinterpret_cast<float*>(sm + SM_SSUM);
    float* s_ssq  = reinterpret_cast<float*>(sm + SM_SSQ);

    const int tid = threadIdx.x;
    const int lane = tid & 31;
    const int wid = tid >> 5;
    const int wm = wid & 1;          // 0..1 : rows wm*32..wm*32+31
    const int wn = wid >> 1;         // 0..3 : cols wn*32..wn*32+31
    const int l7 = lane & 7;
    const int l15 = lane & 15;
    const int lh = lane >> 4;        // A k-half
    const int bkh = (lane >> 3) & 1; // B k-half
    const int bn = ((lane >> 4) << 3) | l7;  // B n-local within 16

    const uint32_t sb = smem_u32(sm);

    // ---- W hi/lo fill (once): [n][k] bf16, 512B pitch, 16B-unit swizzle ----
    for (int idx = tid; idx < 128 * 32; idx += 256) {
        int n = idx >> 5;
        int u = idx & 31;
        int k = u * 8;
        float f[8];
        const float* p = (k < DF) ? (Wself + n * DF + k)
                                  : (Wneigh + n * DF + (k - DF));
        *reinterpret_cast<float4*>(f)     = *reinterpret_cast<const float4*>(p);
        *reinterpret_cast<float4*>(f + 4) = *reinterpret_cast<const float4*>(p + 4);
        uint4 hi, lo;
        cvt8(f, hi, lo);
        uint32_t off = n * 512 + ((u ^ (n & 7)) * 16);
        *reinterpret_cast<uint4*>(sm + SM_WHI + off) = hi;
        *reinterpret_cast<uint4*>(sm + SM_WLO + off) = lo;
    }
    if (tid < DF) {
        s_bc[tid] = __ldg(&b_self[tid]) + __ldg(&bias[tid]);
        s_ssum[tid] = 0.f;
        s_ssq[tid] = 0.f;
    }
    __syncthreads();

    // Precomputed ldmatrix row-base offsets
    uint32_t rowA[2], rowB[2];
#pragma unroll
    for (int mi = 0; mi < 2; mi++)
        rowA[mi] = (uint32_t)(wm * 32 + mi * 16 + l15) * 512;
#pragma unroll
    for (int gi = 0; gi < 2; gi++)
        rowB[gi] = (uint32_t)(wn * 32 + gi * 16 + bn) * 512;

    float st_s[8], st_q[8];
#pragma unroll
    for (int i = 0; i < 8; i++) { st_s[i] = 0.f; st_q[i] = 0.f; }

    const int ntiles = (N + TILE_M - 1) / TILE_M;

    for (int tile = blockIdx.x; tile < ntiles; tile += gridDim.x) {
        const int row0 = tile * TILE_M;

        __syncthreads();   // prior tile's ldmatrix reads done
        // ---- A hi/lo fill: 64 rows x 32 units ----
        for (int idx = tid; idx < TILE_M * 32; idx += 256) {
            int r = idx >> 5;
            int u = idx & 31;
            uint32_t off = r * 512 + ((u ^ (r & 7)) * 16);
            if (row0 + r < N) {
                int k = u * 8;
                const float* p = (k < DF)
                    ? (feat + (size_t)(row0 + r) * DF + k)
                    : (g_neigh + (size_t)(row0 + r) * DF + (k - DF));
                float f[8];
                *reinterpret_cast<float4*>(f)     = *reinterpret_cast<const float4*>(p);
                *reinterpret_cast<float4*>(f + 4) = *reinterpret_cast<const float4*>(p + 4);
                uint4 hi, lo;
                cvt8(f, hi, lo);
                *reinterpret_cast<uint4*>(sm + SM_AHI + off) = hi;
                *reinterpret_cast<uint4*>(sm + SM_ALO + off) = lo;
            } else {
                uint4 z = make_uint4(0, 0, 0, 0);
                *reinterpret_cast<uint4*>(sm + SM_AHI + off) = z;
                *reinterpret_cast<uint4*>(sm + SM_ALO + off) = z;
            }
        }
        __syncthreads();

        float d[2][4][4];
#pragma unroll
        for (int mi = 0; mi < 2; mi++)
#pragma unroll
            for (int t = 0; t < 4; t++)
#pragma unroll
                for (int i = 0; i < 4; i++) d[mi][t][i] = 0.f;

#pragma unroll
        for (int pass = 0; pass < 3; pass++) {
            const uint32_t Ab = sb + ((pass == 2) ? SM_ALO : SM_AHI);
            const uint32_t Wb = sb + ((pass == 1) ? SM_WLO : SM_WHI);
#pragma unroll
            for (int kq = 0; kq < 16; kq++) {
                uint32_t a[2][4], b[2][4];
                uint32_t ua = (uint32_t)(((2 * kq + lh) ^ l7) * 16);
                uint32_t ub = (uint32_t)(((2 * kq + bkh) ^ l7) * 16);
#pragma unroll
                for (int mi = 0; mi < 2; mi++)
                    ldsm4(a[mi][0], a[mi][1], a[mi][2], a[mi][3],
                          Ab + rowA[mi] + ua);
#pragma unroll
                for (int gi = 0; gi < 2; gi++)
                    ldsm4(b[gi][0], b[gi][1], b[gi][2], b[gi][3],
                          Wb + rowB[gi] + ub);
#pragma unroll
                for (int mi = 0; mi < 2; mi++)
#pragma unroll
                    for (int gi = 0; gi < 2; gi++) {
                        mma16816(d[mi][gi * 2 + 0], a[mi][0], a[mi][1],
                                 a[mi][2], a[mi][3], b[gi][0], b[gi][1]);
                        mma16816(d[mi][gi * 2 + 1], a[mi][0], a[mi][1],
                                 a[mi][2], a[mi][3], b[gi][2], b[gi][3]);
                    }
            }
        }

        // ---- Epilogue: bias + ReLU + store + BN stats ----
#pragma unroll
        for (int mi = 0; mi < 2; mi++) {
            int r0g = row0 + wm * 32 + mi * 16 + (lane >> 2);
            int r1g = r0g + 8;
            bool v0 = r0g < N, v1 = r1g < N;
#pragma unroll
            for (int t = 0; t < 4; t++) {
                int cb = wn * 32 + t * 8 + (lane & 3) * 2;
                float x0 = fmaxf(d[mi][t][0] + s_bc[cb],     0.f);
                float x1 = fmaxf(d[mi][t][1] + s_bc[cb + 1], 0.f);
                float x2 = fmaxf(d[mi][t][2] + s_bc[cb],     0.f);
                float x3 = fmaxf(d[mi][t][3] + s_bc[cb + 1], 0.f);
                if (v0) {
                    *reinterpret_cast<float2*>(&out[(size_t)r0g * DF + cb]) =
                        make_float2(x0, x1);
                    st_s[t * 2]     += x0; st_q[t * 2]     += x0 * x0;
                    st_s[t * 2 + 1] += x1; st_q[t * 2 + 1] += x1 * x1;
                }
                if (v1) {
                    *reinterpret_cast<float2*>(&out[(size_t)r1g * DF + cb]) =
                        make_float2(x2, x3);
                    st_s[t * 2]     += x2; st_q[t * 2]     += x2 * x2;
                    st_s[t * 2 + 1] += x3; st_q[t * 2 + 1] += x3 * x3;
                }
            }
        }
    }

    // ---- Flush BN stats: registers -> shared -> global ----
#pragma unroll
    for (int t = 0; t < 4; t++)
#pragma unroll
        for (int c = 0; c < 2; c++) {
            int col = wn * 32 + t * 8 + (lane & 3) * 2 + c;
            atomicAdd(&s_ssum[col], st_s[t * 2 + c]);
            atomicAdd(&s_ssq[col], st_q[t * 2 + c]);
        }
    __syncthreads();
    if (tid < DF) {
        atomicAdd(&g_sum[tid], s_ssum[tid]);
        atomicAdd(&g_sumsq[tid], s_ssq[tid]);
    }

    // ---- Grid-wide barrier (148 blocks, 1/SM resident) ----
    __threadfence();
    __syncthreads();
    if (tid == 0) {
        atomicAdd(&g_bar, 1u);
        while (atomicAdd(&g_bar, 0u) < (unsigned)gridDim.x) __nanosleep(64);
    }
    __syncthreads();
    __threadfence();

    // ---- BN scale/shift (reuse ssum/ssq smem) ----
    if (tid < DF) {
        float invn = 1.0f / (float)N;
        float mu = __ldcg(&g_sum[tid]) * invn;
        float var = __ldcg(&g_sumsq[tid]) * invn - mu * mu;
        float rs = rsqrtf(var + 1e-5f);
        float s = gamma[tid] * rs;
        s_ssum[tid] = s;                       // scale
        s_ssq[tid] = beta[tid] - mu * s;       // shift
    }
    __syncthreads();

    for (int tile = blockIdx.x; tile < ntiles; tile += gridDim.x) {
        const int row0 = tile * TILE_M;
        const int rows = min(TILE_M, N - row0);
        for (int idx = tid; idx < rows * 32; idx += 256) {
            int r = idx >> 5;
            int c4 = (idx & 31) * 4;
            float4* p = reinterpret_cast<float4*>(
                &out[(size_t)(row0 + r) * DF + c4]);
            float4 v = *p;
            float4 s = *reinterpret_cast<float4*>(&s_ssum[c4]);
            float4 h = *reinterpret_cast<float4*>(&s_ssq[c4]);
            v.x = v.x * s.x + h.x;
            v.y = v.y * s.y + h.y;
            v.z = v.z * s.z + h.z;
            v.w = v.w * s.w + h.w;
            *p = v;
        }
    }
}

// ===========================================================================
// Launch
// ===========================================================================
extern "C" void kernel_launch(void* const* d_in, const int* in_sizes, int n_in,
                              void* d_out, int out_size) {
    const float* feat   = (const float*)d_in[0];
    const int*   src    = (const int*)  d_in[1];
    const int*   dst    = (const int*)  d_in[2];
    const float* ew     = (const float*)d_in[3];
    const float* Wneigh = (const float*)d_in[4];
    const float* Wself  = (const float*)d_in[5];
    const float* b_self = (const float*)d_in[6];
    const float* bias   = (const float*)d_in[7];
    const float* gamma  = (const float*)d_in[8];
    const float* beta   = (const float*)d_in[9];
    float* out = (float*)d_out;

    const int N = in_sizes[0] / DF;
    const int E = in_sizes[1];

    cudaFuncSetAttribute(gemm_kernel,
                         cudaFuncAttributeMaxDynamicSharedMemorySize,
                         SMEM_GEMM_BYTES);

    zero_kernel<<<64, 256>>>();
    hist_kernel<<<(E / 4 + 255) / 256, 256>>>(dst, E);
    scan_kernel<<<1, 1024>>>(N);
    scatter_kernel<<<(E + 255) / 256, 256>>>(src, dst, ew, E);
    agg_kernel<<<(N * 32 + 255) / 256, 256>>>(feat, N);
    gemm_kernel<<<GRID_GEMM, 256, SMEM_GEMM_BYTES>>>(feat, Wneigh, Wself, b_self,
                                                     bias, gamma, beta, out, N);
}